// round 16
// baseline (speedup 1.0000x reference)
#include <cuda_runtime.h>
#include <cuda_fp16.h>
#include <cstdint>

// ===== problem constants =====
#define E_   8
#define B_   16384
#define DS_  32
#define DA_  8
#define DIN_ 40
#define HID_ 128
#define TM_  192     // batch rows per CTA (12 warps x 16 rows)
#define NTH_ 384     // 12 warps, 3 per SMSP

// ===== SMEM: fragment-linear single-fp16 weights; k16 block (kc,nt) = 256 B, lane = 8 B =====
#define SM_W0   0                        // 2 kc * 16 nt * 256  = 8192    (states part, k 0..31)
#define SM_W0A  8192                     // 16 nt * 32 lane * 4 = 2048    (actions part, k8)
#define SM_W1   10240                    // 8 kc * 16 nt * 256  = 32768
#define SM_W2   43008                    // 8 kc *  4 nt * 256  = 8192
#define SM_BI   51200                    // b0(512) b1(512) b2(128)
#define SM_STAT 52352                    // 32 slots x 384 thr x 4B = 49152
#define SM_TOTAL (SM_STAT + 49152)       // 101504 bytes

// ===== helpers =====
__device__ __forceinline__ uint32_t packh2(float lo, float hi) {
    uint32_t d;
    asm("cvt.rn.f16x2.f32 %0, %1, %2;" : "=r"(d) : "f"(hi), "f"(lo));
    return d;
}

__device__ __forceinline__ void mma16816(float d[4], const uint32_t a[4],
                                         uint32_t b0, uint32_t b1) {
    asm volatile(
        "mma.sync.aligned.m16n8k16.row.col.f32.f16.f16.f32 "
        "{%0,%1,%2,%3}, {%4,%5,%6,%7}, {%8,%9}, {%0,%1,%2,%3};"
        : "+f"(d[0]), "+f"(d[1]), "+f"(d[2]), "+f"(d[3])
        : "r"(a[0]), "r"(a[1]), "r"(a[2]), "r"(a[3]), "r"(b0), "r"(b1));
}
__device__ __forceinline__ void mma1688(float d[4], uint32_t a0, uint32_t a1,
                                        uint32_t b0) {
    asm volatile(
        "mma.sync.aligned.m16n8k8.row.col.f32.f16.f16.f32 "
        "{%0,%1,%2,%3}, {%4,%5}, {%6}, {%0,%1,%2,%3};"
        : "+f"(d[0]), "+f"(d[1]), "+f"(d[2]), "+f"(d[3])
        : "r"(a0), "r"(a1), "r"(b0));
}

// bias + leaky + fp16 pack of one accumulator ntile
__device__ __forceinline__ void cvt_act(const float acc[4], float2 bb,
                                        uint32_t& h01, uint32_t& h23) {
    float v0 = acc[0] + bb.x, v1 = acc[1] + bb.y;
    float v2 = acc[2] + bb.x, v3 = acc[3] + bb.y;
    v0 = fmaxf(v0, 0.01f * v0); v1 = fmaxf(v1, 0.01f * v1);
    v2 = fmaxf(v2, 0.01f * v2); v3 = fmaxf(v3, 0.01f * v3);
    h01 = packh2(v0, v1);
    h23 = packh2(v2, v3);
}

// stage one weight matrix [Kreal][N] row-major into fragment-linear single-fp16 SMEM
__device__ void stage_w(const float* __restrict__ g, int KC, int NT,
                        int N, char* dst) {
    const int total = KC * NT * 32;
    for (int idx = threadIdx.x; idx < total; idx += NTH_) {
        int lane = idx & 31;
        int blk  = idx >> 5;
        int qk = lane & 3, rr = lane >> 2;
        int nt = blk % NT, kc = blk / NT;
        int n  = nt * 8 + rr;
        int k0 = kc * 16 + qk * 2;
        float f0 = g[(size_t)k0 * N + n];
        float f1 = g[(size_t)(k0 + 1) * N + n];
        float f2 = g[(size_t)(k0 + 8) * N + n];
        float f3 = g[(size_t)(k0 + 9) * N + n];
        uint32_t h01 = packh2(f0, f1);
        uint32_t h23 = packh2(f2, f3);
        *(uint2*)(dst + (size_t)blk * 256 + lane * 8) = make_uint2(h01, h23);
    }
}

__global__ __launch_bounds__(NTH_, 1)
void ensemble_mlp_mma(const float* __restrict__ states,
                      const float* __restrict__ actions,
                      const float* __restrict__ W0, const float* __restrict__ b0,
                      const float* __restrict__ W1, const float* __restrict__ b1,
                      const float* __restrict__ W2, const float* __restrict__ b2,
                      float* __restrict__ out)
{
    extern __shared__ char smc[];
    float* sb0 = (float*)(smc + SM_BI);
    float* sb1 = sb0 + 128;
    float* sb2 = sb1 + 128;
    float* sstat = (float*)(smc + SM_STAT);  // [32 slots][NTH_]: 0..15 sums, 16..31 sqs

    const int tid  = threadIdx.x;
    const int wid  = tid >> 5;
    const int lane = tid & 31;
    const int qk   = lane & 3;     // k-quad within fragment
    const int rr   = lane >> 2;    // row (and B-col) within fragment
    const int j     = blockIdx.y;
    const int btile = blockIdx.x * TM_;
    const int rbase = wid * 16 + rr;

    // ---- stage weights (single fp16) + biases; zero stats ----
    stage_w(W0 + (size_t)j * DIN_ * HID_, 2, 16, HID_, smc + SM_W0);  // k 0..31 (states)
    {   // actions part of W0 (k 32..39) as k8 fragments: single uint32 {h01}
        const float* g = W0 + (size_t)j * DIN_ * HID_;
        for (int idx = tid; idx < 16 * 32; idx += NTH_) {
            int lane2 = idx & 31;
            int nt = idx >> 5;
            int q = lane2 & 3, r2 = lane2 >> 2;
            int n = nt * 8 + r2;
            int k0 = 32 + q * 2;
            float f0 = g[(size_t)k0 * HID_ + n];
            float f1 = g[(size_t)(k0 + 1) * HID_ + n];
            *(uint32_t*)(smc + SM_W0A + (size_t)idx * 4) = packh2(f0, f1);
        }
    }
    stage_w(W1 + (size_t)j * HID_ * HID_, 8, 16, HID_, smc + SM_W1);
    stage_w(W2 + (size_t)j * HID_ * DS_,  8,  4, DS_,  smc + SM_W2);
    if (tid < HID_) { sb0[tid] = b0[j * HID_ + tid]; sb1[tid] = b1[j * HID_ + tid]; }
    if (tid < DS_)  { sb2[tid] = b2[j * DS_ + tid]; }
    #pragma unroll
    for (int s = 0; s < 32; ++s) sstat[s * NTH_ + tid] = 0.f;
    __syncthreads();   // the ONLY barrier — i-loop below is barrier-free

    // per-lane fragment base pointers (inner offsets are compile-time constants)
    const char* w0b  = smc + SM_W0  + lane * 8;
    const char* w0ab = smc + SM_W0A + lane * 4;
    const char* w1b  = smc + SM_W1  + lane * 8;
    const char* w2b  = smc + SM_W2  + lane * 8;
    float* st = sstat + tid;

    // clamped rows for loads (tail CTA); stores guarded at the end
    const int row_lo_g = btile + rbase;
    const int row_lo_c = row_lo_g < B_ - 1 ? row_lo_g : B_ - 1;
    const int row_hi_g = row_lo_g + 8;
    const int row_hi_c = row_hi_g < B_ - 1 ? row_hi_g : B_ - 1;

    const float* srow_lo = states  + (size_t)row_lo_c * DS_ + qk * 2;
    const float* srow_hi = states  + (size_t)row_hi_c * DS_ + qk * 2;
    const float* arow_lo = actions + (size_t)row_lo_c * DA_ + qk * 2;
    const float* arow_hi = actions + (size_t)row_hi_c * DA_ + qk * 2;

    uint32_t aH[32];

    for (int i = 0; i < E_; ++i) {
        // ================= layer 0: K=40 (2x k16 + 1x k8), N=128 =================
        {
            float acc[16][4];
            #pragma unroll
            for (int nt = 0; nt < 16; ++nt)
                #pragma unroll
                for (int t = 0; t < 4; ++t) acc[nt][t] = 0.f;

            // kc = 0,1 : states
            #pragma unroll
            for (int kc = 0; kc < 2; ++kc) {
                float2 x00 = __ldg((const float2*)(srow_lo + kc * 16));
                float2 x01 = __ldg((const float2*)(srow_hi + kc * 16));
                float2 x10 = __ldg((const float2*)(srow_lo + kc * 16 + 8));
                float2 x11 = __ldg((const float2*)(srow_hi + kc * 16 + 8));
                uint32_t ah[4];
                ah[0] = packh2(x00.x, x00.y);
                ah[1] = packh2(x01.x, x01.y);
                ah[2] = packh2(x10.x, x10.y);
                ah[3] = packh2(x11.x, x11.y);
                #pragma unroll
                for (int nt = 0; nt < 16; ++nt) {
                    uint2 bv = *(const uint2*)(w0b + (kc * 16 + nt) * 256);
                    mma16816(acc[nt], ah, bv.x, bv.y);
                }
            }
            // actions: k 32..39 as m16n8k8
            {
                float2 x00 = __ldg((const float2*)(arow_lo));
                float2 x01 = __ldg((const float2*)(arow_hi));
                uint32_t ah0 = packh2(x00.x, x00.y);
                uint32_t ah1 = packh2(x01.x, x01.y);
                #pragma unroll
                for (int nt = 0; nt < 16; ++nt) {
                    uint32_t bv = *(const uint32_t*)(w0ab + nt * 128);
                    mma1688(acc[nt], ah0, ah1, bv);
                }
            }
            #pragma unroll
            for (int nt = 0; nt < 16; ++nt) {
                float2 bb = *(const float2*)(sb0 + nt * 8 + qk * 2);
                cvt_act(acc[nt], bb, aH[2*nt], aH[2*nt+1]);
            }
        }

        // ================= layer 1: K=128, N=128 =================
        {
            float acc[16][4];
            #pragma unroll
            for (int nt = 0; nt < 16; ++nt)
                #pragma unroll
                for (int t = 0; t < 4; ++t) acc[nt][t] = 0.f;

            #pragma unroll
            for (int kc = 0; kc < 8; ++kc) {
                const uint32_t* ah = aH + 4 * kc;
                #pragma unroll
                for (int nt = 0; nt < 16; ++nt) {
                    uint2 bv = *(const uint2*)(w1b + (kc * 16 + nt) * 256);
                    mma16816(acc[nt], ah, bv.x, bv.y);
                }
            }
            #pragma unroll
            for (int nt = 0; nt < 16; ++nt) {
                float2 bb = *(const float2*)(sb1 + nt * 8 + qk * 2);
                cvt_act(acc[nt], bb, aH[2*nt], aH[2*nt+1]);
            }
        }

        // ================= layer 2: K=128, N=32; stats into SMEM =================
        {
            float acc[4][4];
            #pragma unroll
            for (int nt = 0; nt < 4; ++nt)
                #pragma unroll
                for (int t = 0; t < 4; ++t) acc[nt][t] = 0.f;

            #pragma unroll
            for (int kc = 0; kc < 8; ++kc) {
                const uint32_t* ah = aH + 4 * kc;
                #pragma unroll
                for (int nt = 0; nt < 4; ++nt) {
                    uint2 bv = *(const uint2*)(w2b + (kc * 4 + nt) * 256);
                    mma16816(acc[nt], ah, bv.x, bv.y);
                }
            }
            #pragma unroll
            for (int nt = 0; nt < 4; ++nt) {
                float2 bb = *(const float2*)(sb2 + nt * 8 + qk * 2);
                #pragma unroll
                for (int t = 0; t < 4; ++t) {
                    float p = acc[nt][t] + ((t & 1) ? bb.y : bb.x);
                    const int slot = nt * 4 + t;
                    st[slot * NTH_]        += p;
                    st[(16 + slot) * NTH_]  = fmaf(p, p, st[(16 + slot) * NTH_]);
                }
            }
        }

        srow_lo += (size_t)B_ * DS_;
        srow_hi += (size_t)B_ * DS_;
        arow_lo += (size_t)B_ * DA_;
        arow_hi += (size_t)B_ * DA_;
    }

    // ---- epilogue: mean/var over the 8 members; guarded outputs ----
    const size_t var_off = (size_t)E_ * B_ * DS_;
    const bool ok_lo = row_lo_g < B_;
    const bool ok_hi = row_hi_g < B_;
    const size_t row_lo = (size_t)j * B_ + row_lo_g;
    const size_t row_hi = (size_t)j * B_ + row_hi_g;
    #pragma unroll
    for (int nt = 0; nt < 4; ++nt) {
        const int c0 = nt * 8 + qk * 2;
        if (ok_lo) {
            const size_t o = row_lo * DS_ + c0;
            float2 stv = __ldg((const float2*)(states + o));
            float s0 = st[(nt*4+0) * NTH_], s1 = st[(nt*4+1) * NTH_];
            float q0 = st[(16+nt*4+0) * NTH_], q1 = st[(16+nt*4+1) * NTH_];
            float m0 = s0 * 0.125f, m1 = s1 * 0.125f;
            float v0 = (q0 - 8.f * m0 * m0) * (1.f / 7.f);
            float v1 = (q1 - 8.f * m1 * m1) * (1.f / 7.f);
            *(float2*)(out + o)           = make_float2(m0 + stv.x, m1 + stv.y);
            *(float2*)(out + var_off + o) = make_float2(v0, v1);
        }
        if (ok_hi) {
            const size_t o = row_hi * DS_ + c0;
            float2 stv = __ldg((const float2*)(states + o));
            float s2 = st[(nt*4+2) * NTH_], s3 = st[(nt*4+3) * NTH_];
            float q2 = st[(16+nt*4+2) * NTH_], q3 = st[(16+nt*4+3) * NTH_];
            float m2 = s2 * 0.125f, m3 = s3 * 0.125f;
            float v2 = (q2 - 8.f * m2 * m2) * (1.f / 7.f);
            float v3 = (q3 - 8.f * m3 * m3) * (1.f / 7.f);
            *(float2*)(out + o)           = make_float2(m2 + stv.x, m3 + stv.y);
            *(float2*)(out + var_off + o) = make_float2(v2, v3);
        }
    }
}

extern "C" void kernel_launch(void* const* d_in, const int* in_sizes, int n_in,
                              void* d_out, int out_size)
{
    const float* states  = (const float*)d_in[0];
    const float* actions = (const float*)d_in[1];
    const float* W0      = (const float*)d_in[2];
    const float* b0      = (const float*)d_in[3];
    const float* W1      = (const float*)d_in[4];
    const float* b1      = (const float*)d_in[5];
    const float* W2      = (const float*)d_in[6];
    const float* b2      = (const float*)d_in[7];
    float* out = (float*)d_out;

    cudaFuncSetAttribute(ensemble_mlp_mma,
                         cudaFuncAttributeMaxDynamicSharedMemorySize, SM_TOTAL);

    dim3 grid((B_ + TM_ - 1) / TM_, E_);   // 86 x 8 = 688 CTAs
    ensemble_mlp_mma<<<grid, NTH_, SM_TOTAL>>>(states, actions,
                                               W0, b0, W1, b1, W2, b2, out);
}

// round 17
// speedup vs baseline: 1.1291x; 1.1291x over previous
#include <cuda_runtime.h>
#include <cuda_fp16.h>
#include <cstdint>

// ===== problem constants =====
#define E_   8
#define B_   16384
#define DS_  32
#define DA_  8
#define DIN_ 40
#define HID_ 128
#define TM_  128     // batch rows per CTA
#define NTH_ 256     // 8 warps x 16 rows

// ===== SMEM: fragment-linear single-fp16 weights; k16 block (kc,nt) = 256 B, lane = 8 B =====
#define SM_W0   0                        // 2 kc * 16 nt * 256  = 8192    (states part, k 0..31)
#define SM_W0A  8192                     // 16 nt * 32 lane * 4 = 2048    (actions part, k8)
#define SM_W1   10240                    // 8 kc * 16 nt * 256  = 32768
#define SM_W2   43008                    // 8 kc *  4 nt * 256  = 8192
#define SM_BI   51200                    // sb0h(256) sb1h(256) sb2(128)
#define SM_TOTAL (SM_BI + 1152)          // 52352 bytes

// ===== helpers =====
__device__ __forceinline__ uint32_t packh2(float lo, float hi) {
    uint32_t d;
    asm("cvt.rn.f16x2.f32 %0, %1, %2;" : "=r"(d) : "f"(hi), "f"(lo));
    return d;
}

__device__ __forceinline__ void mma16816(float d[4], const uint32_t a[4],
                                         uint32_t b0, uint32_t b1) {
    asm volatile(
        "mma.sync.aligned.m16n8k16.row.col.f32.f16.f16.f32 "
        "{%0,%1,%2,%3}, {%4,%5,%6,%7}, {%8,%9}, {%0,%1,%2,%3};"
        : "+f"(d[0]), "+f"(d[1]), "+f"(d[2]), "+f"(d[3])
        : "r"(a[0]), "r"(a[1]), "r"(a[2]), "r"(a[3]), "r"(b0), "r"(b1));
}
__device__ __forceinline__ void mma1688(float d[4], uint32_t a0, uint32_t a1,
                                        uint32_t b0) {
    asm volatile(
        "mma.sync.aligned.m16n8k8.row.col.f32.f16.f16.f32 "
        "{%0,%1,%2,%3}, {%4,%5}, {%6}, {%0,%1,%2,%3};"
        : "+f"(d[0]), "+f"(d[1]), "+f"(d[2]), "+f"(d[3])
        : "r"(a0), "r"(a1), "r"(b0));
}

// half2-path junction: pack acc to fp16, bias-add + leaky in f16x2
__device__ __forceinline__ void cvt_act_h2(const float acc[4], uint32_t bb,
                                           uint32_t& h01, uint32_t& h23) {
    uint32_t p01 = packh2(acc[0], acc[1]);
    uint32_t p23 = packh2(acc[2], acc[3]);
    const __half2 b2 = *reinterpret_cast<const __half2*>(&bb);
    const __half2 slope = __float2half2_rn(0.01f);
    __half2 v01 = __hadd2(*reinterpret_cast<__half2*>(&p01), b2);
    __half2 v23 = __hadd2(*reinterpret_cast<__half2*>(&p23), b2);
    v01 = __hmax2(v01, __hmul2(v01, slope));
    v23 = __hmax2(v23, __hmul2(v23, slope));
    h01 = *reinterpret_cast<uint32_t*>(&v01);
    h23 = *reinterpret_cast<uint32_t*>(&v23);
}

// stage one weight matrix [Kreal][N] row-major into fragment-linear single-fp16 SMEM
__device__ void stage_w(const float* __restrict__ g, int KC, int NT,
                        int N, char* dst) {
    const int total = KC * NT * 32;
    for (int idx = threadIdx.x; idx < total; idx += NTH_) {
        int lane = idx & 31;
        int blk  = idx >> 5;
        int qk = lane & 3, rr = lane >> 2;
        int nt = blk % NT, kc = blk / NT;
        int n  = nt * 8 + rr;
        int k0 = kc * 16 + qk * 2;
        float f0 = g[(size_t)k0 * N + n];
        float f1 = g[(size_t)(k0 + 1) * N + n];
        float f2 = g[(size_t)(k0 + 8) * N + n];
        float f3 = g[(size_t)(k0 + 9) * N + n];
        uint32_t h01 = packh2(f0, f1);
        uint32_t h23 = packh2(f2, f3);
        *(uint2*)(dst + (size_t)blk * 256 + lane * 8) = make_uint2(h01, h23);
    }
}

__global__ __launch_bounds__(NTH_, 1)
void ensemble_mlp_mma(const float* __restrict__ states,
                      const float* __restrict__ actions,
                      const float* __restrict__ W0, const float* __restrict__ b0,
                      const float* __restrict__ W1, const float* __restrict__ b1,
                      const float* __restrict__ W2, const float* __restrict__ b2,
                      float* __restrict__ out)
{
    extern __shared__ char smc[];
    uint32_t* sb0h = (uint32_t*)(smc + SM_BI);   // 64 packed half2 bias pairs
    uint32_t* sb1h = sb0h + 64;
    float* sb2 = (float*)(sb1h + 64);            // layer-2 bias stays fp32

    const int tid  = threadIdx.x;
    const int wid  = tid >> 5;
    const int lane = tid & 31;
    const int qk   = lane & 3;     // k-quad within fragment
    const int rr   = lane >> 2;    // row (and B-col) within fragment
    const int j     = blockIdx.y;
    const int btile = blockIdx.x * TM_;
    const int rbase = wid * 16 + rr;

    // ---- stage weights (single fp16) + biases ----
    stage_w(W0 + (size_t)j * DIN_ * HID_, 2, 16, HID_, smc + SM_W0);  // k 0..31 (states)
    {   // actions part of W0 (k 32..39) as k8 fragments: single uint32 {h01}
        const float* g = W0 + (size_t)j * DIN_ * HID_;
        for (int idx = tid; idx < 16 * 32; idx += NTH_) {
            int lane2 = idx & 31;
            int nt = idx >> 5;
            int q = lane2 & 3, r2 = lane2 >> 2;
            int n = nt * 8 + r2;
            int k0 = 32 + q * 2;
            float f0 = g[(size_t)k0 * HID_ + n];
            float f1 = g[(size_t)(k0 + 1) * HID_ + n];
            *(uint32_t*)(smc + SM_W0A + (size_t)idx * 4) = packh2(f0, f1);
        }
    }
    stage_w(W1 + (size_t)j * HID_ * HID_, 8, 16, HID_, smc + SM_W1);
    stage_w(W2 + (size_t)j * HID_ * DS_,  8,  4, DS_,  smc + SM_W2);
    if (tid < 64) {
        sb0h[tid] = packh2(b0[j * HID_ + 2 * tid], b0[j * HID_ + 2 * tid + 1]);
        sb1h[tid] = packh2(b1[j * HID_ + 2 * tid], b1[j * HID_ + 2 * tid + 1]);
    }
    if (tid < DS_) { sb2[tid] = b2[j * DS_ + tid]; }
    __syncthreads();   // the ONLY barrier — i-loop below is barrier-free

    // per-lane fragment base pointers (inner offsets are compile-time constants)
    const char* w0b  = smc + SM_W0  + lane * 8;
    const char* w0ab = smc + SM_W0A + lane * 4;
    const char* w1b  = smc + SM_W1  + lane * 8;
    const char* w2b  = smc + SM_W2  + lane * 8;

    // per-thread gmem activation pointers (advance by one i-slice per iter)
    const float* srow = states  + ((size_t)btile + rbase) * DS_ + qk * 2;
    const float* arow = actions + ((size_t)btile + rbase) * DA_ + qk * 2;

    float sums[16], sqs[16];
    #pragma unroll
    for (int t = 0; t < 16; ++t) { sums[t] = 0.f; sqs[t] = 0.f; }

    uint32_t aH[32];

    // ---- preload X for i=0 (raw float2, packed at consumption) ----
    float2 xs[2][4], xact[2];
    #pragma unroll
    for (int kc = 0; kc < 2; ++kc) {
        xs[kc][0] = __ldg((const float2*)(srow + kc * 16));
        xs[kc][1] = __ldg((const float2*)(srow + kc * 16 + 8 * DS_));
        xs[kc][2] = __ldg((const float2*)(srow + kc * 16 + 8));
        xs[kc][3] = __ldg((const float2*)(srow + kc * 16 + 8 + 8 * DS_));
    }
    xact[0] = __ldg((const float2*)(arow));
    xact[1] = __ldg((const float2*)(arow + 8 * DA_));

    for (int i = 0; i < E_; ++i) {
        // ================= layer 0: K=40 (2x k16 + 1x k8), N=128 =================
        {
            float acc[16][4];
            #pragma unroll
            for (int nt = 0; nt < 16; ++nt)
                #pragma unroll
                for (int t = 0; t < 4; ++t) acc[nt][t] = 0.f;

            // pack current X
            uint32_t xr[2][4], xa0, xa1;
            #pragma unroll
            for (int kc = 0; kc < 2; ++kc)
                #pragma unroll
                for (int m = 0; m < 4; ++m)
                    xr[kc][m] = packh2(xs[kc][m].x, xs[kc][m].y);
            xa0 = packh2(xact[0].x, xact[0].y);
            xa1 = packh2(xact[1].x, xact[1].y);

            #pragma unroll
            for (int kc = 0; kc < 2; ++kc)
                #pragma unroll
                for (int nt = 0; nt < 16; ++nt) {
                    uint2 bv = *(const uint2*)(w0b + (kc * 16 + nt) * 256);
                    mma16816(acc[nt], xr[kc], bv.x, bv.y);
                }
            #pragma unroll
            for (int nt = 0; nt < 16; ++nt) {
                uint32_t bv = *(const uint32_t*)(w0ab + nt * 128);
                mma1688(acc[nt], xa0, xa1, bv);
            }

            // ---- prefetch X for i+1 (hidden under layers 0-junction/1/2) ----
            srow += (size_t)B_ * DS_;
            arow += (size_t)B_ * DA_;
            if (i < E_ - 1) {
                #pragma unroll
                for (int kc = 0; kc < 2; ++kc) {
                    xs[kc][0] = __ldg((const float2*)(srow + kc * 16));
                    xs[kc][1] = __ldg((const float2*)(srow + kc * 16 + 8 * DS_));
                    xs[kc][2] = __ldg((const float2*)(srow + kc * 16 + 8));
                    xs[kc][3] = __ldg((const float2*)(srow + kc * 16 + 8 + 8 * DS_));
                }
                xact[0] = __ldg((const float2*)(arow));
                xact[1] = __ldg((const float2*)(arow + 8 * DA_));
            }

            // junction (half2 path)
            #pragma unroll
            for (int nt = 0; nt < 16; ++nt) {
                uint32_t bb = sb0h[nt * 4 + qk];
                cvt_act_h2(acc[nt], bb, aH[2*nt], aH[2*nt+1]);
            }
        }

        // ================= layer 1: K=128, N=128 =================
        {
            float acc[16][4];
            #pragma unroll
            for (int nt = 0; nt < 16; ++nt)
                #pragma unroll
                for (int t = 0; t < 4; ++t) acc[nt][t] = 0.f;

            #pragma unroll
            for (int kc = 0; kc < 8; ++kc) {
                const uint32_t* ah = aH + 4 * kc;
                #pragma unroll
                for (int nt = 0; nt < 16; ++nt) {
                    uint2 bv = *(const uint2*)(w1b + (kc * 16 + nt) * 256);
                    mma16816(acc[nt], ah, bv.x, bv.y);
                }
            }
            #pragma unroll
            for (int nt = 0; nt < 16; ++nt) {
                uint32_t bb = sb1h[nt * 4 + qk];
                cvt_act_h2(acc[nt], bb, aH[2*nt], aH[2*nt+1]);
            }
        }

        // ================= layer 2: K=128, N=32; stats (fp32 path) =================
        {
            float acc[4][4];
            #pragma unroll
            for (int nt = 0; nt < 4; ++nt)
                #pragma unroll
                for (int t = 0; t < 4; ++t) acc[nt][t] = 0.f;

            #pragma unroll
            for (int kc = 0; kc < 8; ++kc) {
                const uint32_t* ah = aH + 4 * kc;
                #pragma unroll
                for (int nt = 0; nt < 4; ++nt) {
                    uint2 bv = *(const uint2*)(w2b + (kc * 4 + nt) * 256);
                    mma16816(acc[nt], ah, bv.x, bv.y);
                }
            }
            #pragma unroll
            for (int nt = 0; nt < 4; ++nt) {
                float2 bb = *(const float2*)(sb2 + nt * 8 + qk * 2);
                float p0 = acc[nt][0] + bb.x;
                float p1 = acc[nt][1] + bb.y;
                float p2 = acc[nt][2] + bb.x;
                float p3 = acc[nt][3] + bb.y;
                sums[nt*4+0] += p0; sqs[nt*4+0] = fmaf(p0, p0, sqs[nt*4+0]);
                sums[nt*4+1] += p1; sqs[nt*4+1] = fmaf(p1, p1, sqs[nt*4+1]);
                sums[nt*4+2] += p2; sqs[nt*4+2] = fmaf(p2, p2, sqs[nt*4+2]);
                sums[nt*4+3] += p3; sqs[nt*4+3] = fmaf(p3, p3, sqs[nt*4+3]);
            }
        }
    }

    // ---- epilogue: mean/var over the 8 members; outputs ----
    const size_t var_off = (size_t)E_ * B_ * DS_;
    const size_t row_lo = (size_t)j * B_ + btile + rbase;
    const size_t row_hi = row_lo + 8;
    #pragma unroll
    for (int nt = 0; nt < 4; ++nt) {
        const int c0 = nt * 8 + qk * 2;
        {
            const size_t o = row_lo * DS_ + c0;
            float2 st = __ldg((const float2*)(states + o));
            float m0 = sums[nt*4+0] * 0.125f;
            float m1 = sums[nt*4+1] * 0.125f;
            float v0 = (sqs[nt*4+0] - 8.f * m0 * m0) * (1.f / 7.f);
            float v1 = (sqs[nt*4+1] - 8.f * m1 * m1) * (1.f / 7.f);
            *(float2*)(out + o)           = make_float2(m0 + st.x, m1 + st.y);
            *(float2*)(out + var_off + o) = make_float2(v0, v1);
        }
        {
            const size_t o = row_hi * DS_ + c0;
            float2 st = __ldg((const float2*)(states + o));
            float m2 = sums[nt*4+2] * 0.125f;
            float m3 = sums[nt*4+3] * 0.125f;
            float v2 = (sqs[nt*4+2] - 8.f * m2 * m2) * (1.f / 7.f);
            float v3 = (sqs[nt*4+3] - 8.f * m3 * m3) * (1.f / 7.f);
            *(float2*)(out + o)           = make_float2(m2 + st.x, m3 + st.y);
            *(float2*)(out + var_off + o) = make_float2(v2, v3);
        }
    }
}

extern "C" void kernel_launch(void* const* d_in, const int* in_sizes, int n_in,
                              void* d_out, int out_size)
{
    const float* states  = (const float*)d_in[0];
    const float* actions = (const float*)d_in[1];
    const float* W0      = (const float*)d_in[2];
    const float* b0      = (const float*)d_in[3];
    const float* W1      = (const float*)d_in[4];
    const float* b1      = (const float*)d_in[5];
    const float* W2      = (const float*)d_in[6];
    const float* b2      = (const float*)d_in[7];
    float* out = (float*)d_out;

    cudaFuncSetAttribute(ensemble_mlp_mma,
                         cudaFuncAttributeMaxDynamicSharedMemorySize, SM_TOTAL);

    dim3 grid(B_ / TM_, E_);   // 128 x 8 = 1024 CTAs
    ensemble_mlp_mma<<<grid, NTH_, SM_TOTAL>>>(states, actions,
                                               W0, b0, W1, b1, W2, b2, out);
}